// round 3
// baseline (speedup 1.0000x reference)
#include <cuda_runtime.h>
#include <math.h>

#define BB   64
#define SS   512
#define EMBD 128
#define HIDD 256
#define G4   1024
#define NT   9

// Scratch (allocation-free rule: __device__ globals)
__device__ float g_xz[(size_t)2*SS*G4*BB];     // [dir][t][col(1024)][b(64)]  256 MB
__device__ float g_hbuf[(size_t)2*SS*HIDD*BB]; // [dir][t][j(256)][b(64)]      64 MB
__device__ int   g_bar_count;
__device__ int   g_bar_sense;

// ---------------------------------------------------------------------------
// K1: xz[dir][t][col][b] = emb[text[b][t]] @ W_{f,b} + b_{f,b}
// grid (512 t-tiles, 16 n-tiles of 128), 256 thr, tile M=64(b) x N=128, K=128
// ---------------------------------------------------------------------------
__global__ __launch_bounds__(256, 1) void gemm_xz_kernel(
    const int* __restrict__ text, const float* __restrict__ emb,
    const float* __restrict__ W_f, const float* __restrict__ b_f,
    const float* __restrict__ W_b, const float* __restrict__ b_b)
{
    extern __shared__ float sm[];
    float* A_sh = sm;             // [128 k][68]  (A[k][b])
    float* B_sh = sm + 128 * 68;  // [128 k][136] (B[k][n])
    __shared__ int tok[64];

    const int tid = threadIdx.x;
    const int t   = blockIdx.x;
    const int by  = blockIdx.y;
    const int dir = by >> 3;
    const float* W    = dir ? W_b : W_f;
    const float* bias = dir ? b_b : b_f;
    const int colbase = (by & 7) * 128;

    if (tid < 64) tok[tid] = text[tid * SS + t];
    __syncthreads();

    // Gather A (transposed): A_sh[k][b] = emb[tok[b]][k]
    {
        const int b = tid >> 2, seg = tid & 3;
        const float4* er = (const float4*)(emb + (size_t)tok[b] * EMBD);
        #pragma unroll
        for (int i = 0; i < 8; ++i) {
            float4 v = er[seg * 8 + i];
            int k0 = (seg * 8 + i) * 4;
            A_sh[(k0 + 0) * 68 + b] = v.x;
            A_sh[(k0 + 1) * 68 + b] = v.y;
            A_sh[(k0 + 2) * 68 + b] = v.z;
            A_sh[(k0 + 3) * 68 + b] = v.w;
        }
    }
    // Load B: B_sh[k][0..127] = W[k][colbase..colbase+127]
    {
        const int k = tid >> 1, half = tid & 1;
        const float4* wr = (const float4*)(W + (size_t)k * G4 + colbase + half * 64);
        float4* br = (float4*)(B_sh + k * 136 + half * 64);
        #pragma unroll
        for (int i = 0; i < 16; ++i) br[i] = wr[i];
    }
    __syncthreads();

    const int ty = tid >> 5, tx = tid & 31;   // micro-tile: 8 b-rows x 4 cols
    float acc[8][4];
    #pragma unroll
    for (int i = 0; i < 8; ++i)
        #pragma unroll
        for (int j = 0; j < 4; ++j) acc[i][j] = 0.f;

    #pragma unroll 4
    for (int k = 0; k < 128; ++k) {
        float4 a0 = *(const float4*)&A_sh[k * 68 + ty * 8];
        float4 a1 = *(const float4*)&A_sh[k * 68 + ty * 8 + 4];
        float4 b4 = *(const float4*)&B_sh[k * 136 + tx * 4];
        float av[8] = {a0.x, a0.y, a0.z, a0.w, a1.x, a1.y, a1.z, a1.w};
        float bv[4] = {b4.x, b4.y, b4.z, b4.w};
        #pragma unroll
        for (int i = 0; i < 8; ++i)
            #pragma unroll
            for (int j = 0; j < 4; ++j) acc[i][j] = fmaf(av[i], bv[j], acc[i][j]);
    }

    #pragma unroll
    for (int j = 0; j < 4; ++j) {
        const int col = colbase + tx * 4 + j;
        const float bj = bias[col];
        float* dst = &g_xz[(((size_t)dir * SS + t) * G4 + col) * BB + ty * 8];
        float4 lo = make_float4(acc[0][j] + bj, acc[1][j] + bj, acc[2][j] + bj, acc[3][j] + bj);
        float4 hi = make_float4(acc[4][j] + bj, acc[5][j] + bj, acc[6][j] + bj, acc[7][j] + bj);
        *(float4*)dst       = lo;
        *(float4*)(dst + 4) = hi;
    }
}

// ---------------------------------------------------------------------------
// K2: persistent BiLSTM. 128 blocks (64/dir), 256 thr, 1 grid barrier / step.
// Block owns 4 hidden columns (all 4 gates) for all 64 batches; c in registers.
// Dot phase: warp = k-slice (8-way k split), thread = (8 b's) x (4 gates).
// ---------------------------------------------------------------------------
__global__ __launch_bounds__(256, 1) void lstm_kernel(
    const float* __restrict__ U_f, const float* __restrict__ U_b)
{
    extern __shared__ float sm[];
    float* h_sh = sm;                         // [256 k][64 b]
    float* U_sh = sm + 256 * 64;              // [256 k][16]  (col = jj*4+gate)
    float* red  = sm + 256 * 64 + 256 * 16;   // [256 thr][36]

    const int tid = threadIdx.x;
    const int dir = blockIdx.x >> 6;
    const int jb  = (blockIdx.x & 63) * 4;
    const float* Ug = dir ? U_b : U_f;

    // U tile once (constant across steps)
    for (int idx = tid; idx < 4096; idx += 256) {
        int k = idx >> 4, l = idx & 15;       // l = jj*4 + g
        U_sh[idx] = Ug[(size_t)k * G4 + (l & 3) * HIDD + jb + (l >> 2)];
    }

    // dot-phase roles
    const int kr = tid >> 5, u = tid & 31;
    const int bgd = u >> 2, jjd = u & 3;
    // update-phase roles
    const int bu = tid & 63, jju = tid >> 6;
    const int ju = jb + jju;
    const int bg2 = bu >> 3, bi2 = bu & 7;

    float creg = 0.f;
    const int base = *((volatile int*)&g_bar_sense);

    for (int s = 0; s < SS; ++s) {
        const int t = dir ? (SS - 1 - s) : s;

        // stage h_{t-1} into shared (transposed [k][b]); zeros at s==0
        if (s == 0) {
            #pragma unroll
            for (int i = 0; i < 16; ++i)
                ((float4*)h_sh)[tid + i * 256] = make_float4(0.f, 0.f, 0.f, 0.f);
        } else {
            const int tp = dir ? (t + 1) : (t - 1);
            const float4* src = (const float4*)&g_hbuf[(((size_t)dir * SS + tp) * HIDD) * BB];
            #pragma unroll
            for (int i = 0; i < 16; ++i)
                ((float4*)h_sh)[tid + i * 256] = src[tid + i * 256];
        }
        __syncthreads();

        // partial dots over this warp's k-slice
        float acc[8][4];
        #pragma unroll
        for (int i = 0; i < 8; ++i)
            #pragma unroll
            for (int g = 0; g < 4; ++g) acc[i][g] = 0.f;

        const int kbase = kr * 32;
        #pragma unroll 4
        for (int kk = 0; kk < 32; ++kk) {
            const int k = kbase + kk;
            float4 u4 = *(const float4*)&U_sh[k * 16 + jjd * 4];
            float4 h0 = *(const float4*)&h_sh[k * 64 + bgd * 8];
            float4 h1 = *(const float4*)&h_sh[k * 64 + bgd * 8 + 4];
            float hv[8] = {h0.x, h0.y, h0.z, h0.w, h1.x, h1.y, h1.z, h1.w};
            float uv[4] = {u4.x, u4.y, u4.z, u4.w};
            #pragma unroll
            for (int bi = 0; bi < 8; ++bi)
                #pragma unroll
                for (int g = 0; g < 4; ++g)
                    acc[bi][g] = fmaf(hv[bi], uv[g], acc[bi][g]);
        }
        {
            float* rr = &red[tid * 36];
            #pragma unroll
            for (int a = 0; a < 32; ++a) rr[a] = acc[a >> 2][a & 3];
        }
        __syncthreads();

        // combine k-slices + gate math + state update (thread = one (b, j))
        const float* xzb = &g_xz[(((size_t)dir * SS + t) * G4) * BB];
        float z0 = xzb[(0 * HIDD + ju) * BB + bu];
        float z1 = xzb[(1 * HIDD + ju) * BB + bu];
        float z2 = xzb[(2 * HIDD + ju) * BB + bu];
        float z3 = xzb[(3 * HIDD + ju) * BB + bu];
        #pragma unroll
        for (int k2 = 0; k2 < 8; ++k2) {
            const float* rr = &red[(k2 * 32 + bg2 * 4 + jju) * 36 + bi2 * 4];
            z0 += rr[0]; z1 += rr[1]; z2 += rr[2]; z3 += rr[3];
        }
        const float ig = 1.f / (1.f + expf(-z0));
        const float fg = 1.f / (1.f + expf(-z1));
        const float gg = tanhf(z2);
        const float og = 1.f / (1.f + expf(-z3));
        creg = fg * creg + ig * gg;
        const float h = og * tanhf(creg);
        g_hbuf[(((size_t)dir * SS + t) * HIDD + ju) * BB + bu] = h;

        // grid barrier (sense-reversing; 128 co-resident blocks)
        __syncthreads();
        if (tid == 0) {
            __threadfence();
            if (atomicAdd(&g_bar_count, 1) == 127) {
                g_bar_count = 0;
                __threadfence();
                *((volatile int*)&g_bar_sense) = base + s + 1;
            } else {
                while (*((volatile int*)&g_bar_sense) != base + s + 1) {}
            }
            __threadfence();
        }
        __syncthreads();
    }
}

// ---------------------------------------------------------------------------
// K3: logits[b][t][tag] = concat(h_f,h_b)[t,:,b] @ W_d + b_d. Block per t.
// ---------------------------------------------------------------------------
__global__ __launch_bounds__(256) void logits_kernel(
    const float* __restrict__ W_d, const float* __restrict__ b_d,
    float* __restrict__ out)
{
    __shared__ float Wd_sh[512 * 9];
    __shared__ float red2[256 * 9];
    const int tid = threadIdx.x, t = blockIdx.x;

    for (int idx = tid; idx < 512 * 9; idx += 256) Wd_sh[idx] = W_d[idx];
    __syncthreads();

    const int jg = tid >> 6, b = tid & 63;
    const int dir = jg >> 1;
    const int j0 = (jg & 1) * 128;
    const float* hsrc = &g_hbuf[(((size_t)dir * SS + t) * HIDD) * BB];

    float acc[9];
    #pragma unroll
    for (int q = 0; q < 9; ++q) acc[q] = 0.f;

    for (int i = 0; i < 128; ++i) {
        const int j = j0 + i;
        const float hv = hsrc[j * BB + b];
        const float* w = &Wd_sh[(dir * 256 + j) * 9];
        #pragma unroll
        for (int q = 0; q < 9; ++q) acc[q] = fmaf(hv, w[q], acc[q]);
    }
    #pragma unroll
    for (int q = 0; q < 9; ++q) red2[tid * 9 + q] = acc[q];
    __syncthreads();

    if (tid < 64) {
        const int bb = tid;
        #pragma unroll
        for (int q = 0; q < 9; ++q) {
            float v = b_d[q];
            #pragma unroll
            for (int g = 0; g < 4; ++g) v += red2[(g * 64 + bb) * 9 + q];
            out[((size_t)bb * SS + t) * NT + q] = v;
        }
    }
}

// ---------------------------------------------------------------------------
// K4: CRF log-norm + sequence score + lens. One warp per batch row.
// out layout: [logits 294912][text_lens 64][log_likelihood 64]
// ---------------------------------------------------------------------------
__global__ __launch_bounds__(32) void crf_kernel(
    const int* __restrict__ text, const int* __restrict__ labels,
    const float* __restrict__ trans, float* __restrict__ out)
{
    const int b = blockIdx.x, lane = threadIdx.x;
    const float* logits = out;
    const unsigned FULL = 0xFFFFFFFFu;

    // sequence length = count(text != 0)
    int cnt = 0;
    for (int s = lane; s < SS; s += 32) cnt += (text[b * SS + s] != 0);
    #pragma unroll
    for (int o = 16; o; o >>= 1) cnt += __shfl_xor_sync(FULL, cnt, o);
    const int len = cnt;

    // lane j holds column j of trans
    float tr[9];
    #pragma unroll
    for (int i = 0; i < 9; ++i) tr[i] = (lane < 9) ? trans[i * 9 + lane] : 0.f;

    float alpha = (lane < 9) ? logits[((size_t)b * SS) * NT + lane] : -1e30f;

    for (int t = 1; t < SS; ++t) {
        float v[9];
        float m = -1e30f;
        #pragma unroll
        for (int i = 0; i < 9; ++i) {
            const float ai = __shfl_sync(FULL, alpha, i);
            v[i] = ai + tr[i];
            m = fmaxf(m, v[i]);
        }
        float ssum = 0.f;
        #pragma unroll
        for (int i = 0; i < 9; ++i) ssum += __expf(v[i] - m);
        const float lg = (lane < 9) ? logits[((size_t)b * SS + t) * NT + lane] : 0.f;
        const float nv = m + __logf(ssum) + lg;
        if (t < len && lane < 9) alpha = nv;
    }

    // log-norm = logsumexp over tags
    float av = (lane < 9) ? alpha : -1e30f;
    float m = av;
    #pragma unroll
    for (int o = 16; o; o >>= 1) m = fmaxf(m, __shfl_xor_sync(FULL, m, o));
    float e = (lane < 9) ? __expf(av - m) : 0.f;
    #pragma unroll
    for (int o = 16; o; o >>= 1) e += __shfl_xor_sync(FULL, e, o);
    const float lognorm = m + __logf(e);

    // sequence score
    float sc = 0.f;
    for (int t = lane; t < SS; t += 32) {
        const int lt = labels[b * SS + t];
        if (t < len) sc += logits[((size_t)b * SS + t) * NT + lt];
        if (t < len - 1) sc += trans[lt * 9 + labels[b * SS + t + 1]];
    }
    #pragma unroll
    for (int o = 16; o; o >>= 1) sc += __shfl_xor_sync(FULL, sc, o);

    if (lane == 0) {
        out[(size_t)BB * SS * NT + b]      = (float)len;   // text_lens
        out[(size_t)BB * SS * NT + BB + b] = sc - lognorm; // log_likelihood
    }
}

// ---------------------------------------------------------------------------
extern "C" void kernel_launch(void* const* d_in, const int* in_sizes, int n_in,
                              void* d_out, int out_size)
{
    const int*   text   = (const int*)  d_in[0];
    const int*   labels = (const int*)  d_in[1];
    const float* emb    = (const float*)d_in[2];
    const float* W_f    = (const float*)d_in[3];
    const float* U_f    = (const float*)d_in[4];
    const float* b_f    = (const float*)d_in[5];
    const float* W_b    = (const float*)d_in[6];
    const float* U_b    = (const float*)d_in[7];
    const float* b_b    = (const float*)d_in[8];
    const float* W_d    = (const float*)d_in[9];
    const float* b_d    = (const float*)d_in[10];
    const float* trans  = (const float*)d_in[11];
    float* out = (float*)d_out;

    cudaFuncSetAttribute(gemm_xz_kernel, cudaFuncAttributeMaxDynamicSharedMemorySize, 104448);
    cudaFuncSetAttribute(lstm_kernel,    cudaFuncAttributeMaxDynamicSharedMemorySize, 118784);

    gemm_xz_kernel<<<dim3(512, 16), 256, 104448>>>(text, emb, W_f, b_f, W_b, b_b);
    lstm_kernel<<<128, 256, 118784>>>(U_f, U_b);
    logits_kernel<<<512, 256>>>(W_d, b_d, out);
    crf_kernel<<<64, 32>>>(text, labels, trans, out);
}

// round 4
// speedup vs baseline: 1.0194x; 1.0194x over previous
#include <cuda_runtime.h>
#include <math.h>

#define BB   64
#define SS   512
#define EMBD 128
#define HIDD 256
#define G4   1024
#define NT   9

// Scratch (allocation-free rule: __device__ globals)
__device__ float g_xz[(size_t)2*SS*G4*BB];     // [dir][t][col(1024)][b(64)]
__device__ float g_hbuf[(size_t)2*SS*HIDD*BB]; // [dir][t][j(256)][b(64)]
__device__ int   g_bar_count;
__device__ int   g_bar_sense;

// ---- packed f32x2 helpers (exact: two independent fp32 FMAs per instr) ----
__device__ __forceinline__ void ffma2(unsigned long long& d, unsigned long long a, unsigned long long b){
    asm("fma.rn.f32x2 %0, %1, %2, %0;" : "+l"(d) : "l"(a), "l"(b));
}
__device__ __forceinline__ unsigned long long pack2(float lo, float hi){
    unsigned long long r; asm("mov.b64 %0, {%1, %2};" : "=l"(r) : "f"(lo), "f"(hi)); return r;
}
__device__ __forceinline__ unsigned long long addf2(unsigned long long a, unsigned long long b){
    unsigned long long r; asm("add.rn.f32x2 %0, %1, %2;" : "=l"(r) : "l"(a), "l"(b)); return r;
}
// ---- acquire/release barrier primitives ----
__device__ __forceinline__ int atom_add_acqrel(int* p, int v){
    int old; asm volatile("atom.add.acq_rel.gpu.global.s32 %0, [%1], %2;" : "=r"(old) : "l"(p), "r"(v) : "memory"); return old;
}
__device__ __forceinline__ int ld_acq(const int* p){
    int v; asm volatile("ld.acquire.gpu.global.s32 %0, [%1];" : "=r"(v) : "l"(p) : "memory"); return v;
}
__device__ __forceinline__ void st_rel(int* p, int v){
    asm volatile("st.release.gpu.global.s32 [%0], %1;" :: "l"(p), "r"(v) : "memory");
}

// ---------------------------------------------------------------------------
// K1: xz[dir][t][col][b] = emb[text[b][t]] @ W_{f,b} + b_{f,b}
// grid (512, 16), 256 thr, tile M=64(b) x N=128(col), K=128. FFMA2 b-pair packed.
// ---------------------------------------------------------------------------
__global__ __launch_bounds__(256, 2) void gemm_xz_kernel(
    const int* __restrict__ text, const float* __restrict__ emb,
    const float* __restrict__ W_f, const float* __restrict__ b_f,
    const float* __restrict__ W_b, const float* __restrict__ b_b)
{
    extern __shared__ float sm[];
    float* A_sh = sm;             // [128 k][68]  (A[k][b])
    float* B_sh = sm + 128 * 68;  // [128 k][132] (B[k][n])
    __shared__ int tok[64];

    const int tid = threadIdx.x;
    const int t   = blockIdx.x;
    const int by  = blockIdx.y;
    const int dir = by >> 3;
    const float* W    = dir ? W_b : W_f;
    const float* bias = dir ? b_b : b_f;
    const int colbase = (by & 7) * 128;

    if (tid < 64) tok[tid] = text[tid * SS + t];
    __syncthreads();

    // Gather A (transposed): A_sh[k][b] = emb[tok[b]][k]
    {
        const int b = tid >> 2, seg = tid & 3;
        const float4* er = (const float4*)(emb + (size_t)tok[b] * EMBD);
        #pragma unroll
        for (int i = 0; i < 8; ++i) {
            float4 v = er[seg * 8 + i];
            int k0 = (seg * 8 + i) * 4;
            A_sh[(k0 + 0) * 68 + b] = v.x;
            A_sh[(k0 + 1) * 68 + b] = v.y;
            A_sh[(k0 + 2) * 68 + b] = v.z;
            A_sh[(k0 + 3) * 68 + b] = v.w;
        }
    }
    // Load B: B_sh[k][0..127] = W[k][colbase..colbase+127]
    {
        const int k = tid >> 1, half = tid & 1;
        const float4* wr = (const float4*)(W + (size_t)k * G4 + colbase + half * 64);
        float4* br = (float4*)(B_sh + k * 132 + half * 64);
        #pragma unroll
        for (int i = 0; i < 16; ++i) br[i] = wr[i];
    }
    __syncthreads();

    const int ty = tid >> 5, tx = tid & 31;   // micro-tile: 8 b (4 pairs) x 4 cols
    unsigned long long acc[4][4];             // [b-pair][j], halves = (b even, b odd)
    #pragma unroll
    for (int i = 0; i < 4; ++i)
        #pragma unroll
        for (int j = 0; j < 4; ++j) acc[i][j] = 0ull;

    #pragma unroll 4
    for (int k = 0; k < 128; ++k) {
        const ulonglong2 a01 = *(const ulonglong2*)&A_sh[k * 68 + ty * 8];
        const ulonglong2 a23 = *(const ulonglong2*)&A_sh[k * 68 + ty * 8 + 4];
        const float4 b4 = *(const float4*)&B_sh[k * 132 + tx * 4];
        unsigned long long ap[4] = {a01.x, a01.y, a23.x, a23.y};
        unsigned long long bd[4] = {pack2(b4.x, b4.x), pack2(b4.y, b4.y),
                                    pack2(b4.z, b4.z), pack2(b4.w, b4.w)};
        #pragma unroll
        for (int i = 0; i < 4; ++i)
            #pragma unroll
            for (int j = 0; j < 4; ++j) ffma2(acc[i][j], ap[i], bd[j]);
    }

    const float4 bv = *(const float4*)&bias[colbase + tx * 4];
    const float bj[4] = {bv.x, bv.y, bv.z, bv.w};
    #pragma unroll
    for (int j = 0; j < 4; ++j) {
        const int col = colbase + tx * 4 + j;
        const unsigned long long bj2 = pack2(bj[j], bj[j]);
        float* dst = &g_xz[(((size_t)dir * SS + t) * G4 + col) * BB + ty * 8];
        ulonglong2 lo = make_ulonglong2(addf2(acc[0][j], bj2), addf2(acc[1][j], bj2));
        ulonglong2 hi = make_ulonglong2(addf2(acc[2][j], bj2), addf2(acc[3][j], bj2));
        *(ulonglong2*)dst       = lo;
        *(ulonglong2*)(dst + 4) = hi;
    }
}

// ---------------------------------------------------------------------------
// K2: persistent BiLSTM. 128 blocks (64/dir), 256 thr, 1 grid barrier / step.
// Block owns 4 hidden cols (16 gate cols). Dot: thread=(b, k-quarter) covers
// ALL 16 gate cols with FFMA2 gate-pairs; small 4-way k reduction in shared.
// ---------------------------------------------------------------------------
__global__ __launch_bounds__(256, 1) void lstm_kernel(
    const float* __restrict__ U_f, const float* __restrict__ U_b)
{
    extern __shared__ float sm[];
    float* h_sh = sm;                         // [256 k][64 b]   65536 B
    float* U_sh = sm + 256 * 64;              // [256 k][16]     16384 B
    float* red  = sm + 256 * 64 + 256 * 16;   // [256 thr][20]   20480 B

    const int tid = threadIdx.x;
    const int dir = blockIdx.x >> 6;
    const int jb  = (blockIdx.x & 63) * 4;
    const float* Ug = dir ? U_b : U_f;

    // U tile once (constant across steps): U_sh[k][jj*4+g] = U[k][g*256+jb+jj]
    for (int idx = tid; idx < 4096; idx += 256) {
        int k = idx >> 4, l = idx & 15;
        U_sh[idx] = Ug[(size_t)k * G4 + (l & 3) * HIDD + jb + (l >> 2)];
    }

    const int bu = tid & 63;        // batch index (dot + combine)
    const int kh = tid >> 6;        // k-quarter (dot) == jj (combine)
    const int kbase = kh * 64;
    const int ju = jb + kh;

    float creg = 0.f;
    const int base = ld_acq(&g_bar_sense);

    for (int s = 0; s < SS; ++s) {
        const int t = dir ? (SS - 1 - s) : s;

        // stage h_{t-1} into shared [k][b]; zeros at s==0
        if (s == 0) {
            #pragma unroll
            for (int i = 0; i < 16; ++i)
                ((float4*)h_sh)[tid + i * 256] = make_float4(0.f, 0.f, 0.f, 0.f);
        } else {
            const int tp = dir ? (t + 1) : (t - 1);
            const float4* src = (const float4*)&g_hbuf[(((size_t)dir * SS + tp) * HIDD) * BB];
            #pragma unroll
            for (int i = 0; i < 16; ++i)
                ((float4*)h_sh)[tid + i * 256] = src[tid + i * 256];
        }
        __syncthreads();

        // prefetch xz (consumed ~2500 cyc later in combine; hides DRAM)
        const float* xzb = &g_xz[(((size_t)dir * SS + t) * G4) * BB];
        float z0 = xzb[(0 * HIDD + ju) * BB + bu];
        float z1 = xzb[(1 * HIDD + ju) * BB + bu];
        float z2 = xzb[(2 * HIDD + ju) * BB + bu];
        float z3 = xzb[(3 * HIDD + ju) * BB + bu];

        // dot over this thread's k-quarter, all 16 gate cols of batch bu
        unsigned long long acc[4][2];
        #pragma unroll
        for (int jj = 0; jj < 4; ++jj) { acc[jj][0] = 0ull; acc[jj][1] = 0ull; }

        #pragma unroll 4
        for (int kk = 0; kk < 64; ++kk) {
            const int k = kbase + kk;
            const float hv = h_sh[k * 64 + bu];
            const unsigned long long h2 = pack2(hv, hv);
            const ulonglong2* up = (const ulonglong2*)&U_sh[k * 16];
            #pragma unroll
            for (int jj = 0; jj < 4; ++jj) {
                ulonglong2 u = up[jj];
                ffma2(acc[jj][0], h2, u.x);   // gates (0,1)
                ffma2(acc[jj][1], h2, u.y);   // gates (2,3)
            }
        }
        #pragma unroll
        for (int jj = 0; jj < 4; ++jj)
            *(ulonglong2*)&red[tid * 20 + jj * 4] = make_ulonglong2(acc[jj][0], acc[jj][1]);
        __syncthreads();

        // combine 4 k-quarters: thread (bu, jj=kh)
        #pragma unroll
        for (int q = 0; q < 4; ++q) {
            float4 r = *(const float4*)&red[(q * 64 + bu) * 20 + kh * 4];
            z0 += r.x; z1 += r.y; z2 += r.z; z3 += r.w;
        }
        const float ig = 1.f / (1.f + expf(-z0));
        const float fg = 1.f / (1.f + expf(-z1));
        const float gg = tanhf(z2);
        const float og = 1.f / (1.f + expf(-z3));
        creg = fg * creg + ig * gg;
        const float h = og * tanhf(creg);
        g_hbuf[(((size_t)dir * SS + t) * HIDD + ju) * BB + bu] = h;

        // grid barrier (acq/rel, 128 co-resident blocks)
        __syncthreads();
        if (tid == 0) {
            const int target = base + s + 1;
            int old = atom_add_acqrel(&g_bar_count, 1);
            if (old == 127) {
                *((volatile int*)&g_bar_count) = 0;
                st_rel(&g_bar_sense, target);
            } else {
                while (ld_acq(&g_bar_sense) - target < 0) {}
            }
        }
        __syncthreads();
    }
}

// ---------------------------------------------------------------------------
// K3: logits[b][t][tag] = concat(h_f,h_b)[t,:,b] @ W_d + b_d. Block per t.
// ---------------------------------------------------------------------------
__global__ __launch_bounds__(256) void logits_kernel(
    const float* __restrict__ W_d, const float* __restrict__ b_d,
    float* __restrict__ out)
{
    __shared__ float Wd_sh[512 * 9];
    __shared__ float red2[256 * 9];
    const int tid = threadIdx.x, t = blockIdx.x;

    for (int idx = tid; idx < 512 * 9; idx += 256) Wd_sh[idx] = W_d[idx];
    __syncthreads();

    const int jg = tid >> 6, b = tid & 63;
    const int dir = jg >> 1;
    const int j0 = (jg & 1) * 128;
    const float* hsrc = &g_hbuf[(((size_t)dir * SS + t) * HIDD) * BB];

    float acc[9];
    #pragma unroll
    for (int q = 0; q < 9; ++q) acc[q] = 0.f;

    for (int i = 0; i < 128; ++i) {
        const int j = j0 + i;
        const float hv = hsrc[j * BB + b];
        const float* w = &Wd_sh[(dir * 256 + j) * 9];
        #pragma unroll
        for (int q = 0; q < 9; ++q) acc[q] = fmaf(hv, w[q], acc[q]);
    }
    #pragma unroll
    for (int q = 0; q < 9; ++q) red2[tid * 9 + q] = acc[q];
    __syncthreads();

    if (tid < 64) {
        const int bb = tid;
        #pragma unroll
        for (int q = 0; q < 9; ++q) {
            float v = b_d[q];
            #pragma unroll
            for (int g = 0; g < 4; ++g) v += red2[(g * 64 + bb) * 9 + q];
            out[((size_t)bb * SS + t) * NT + q] = v;
        }
    }
}

// ---------------------------------------------------------------------------
// K4: CRF. One warp per batch row. Prefetched logits, tree max/sum.
// out layout: [logits 294912][text_lens 64][log_likelihood 64]
// ---------------------------------------------------------------------------
__global__ __launch_bounds__(32) void crf_kernel(
    const int* __restrict__ text, const int* __restrict__ labels,
    const float* __restrict__ trans, float* __restrict__ out)
{
    const int b = blockIdx.x, lane = threadIdx.x;
    const float* logits = out;
    const unsigned FULL = 0xFFFFFFFFu;

    int cnt = 0;
    for (int s = lane; s < SS; s += 32) cnt += (text[b * SS + s] != 0);
    #pragma unroll
    for (int o = 16; o; o >>= 1) cnt += __shfl_xor_sync(FULL, cnt, o);
    const int len = cnt;

    float tr[9];
    #pragma unroll
    for (int i = 0; i < 9; ++i) tr[i] = (lane < 9) ? trans[i * 9 + lane] : 0.f;

    float alpha = (lane < 9) ? logits[((size_t)b * SS) * NT + lane] : -1e30f;
    float lgnext = (lane < 9) ? __ldg(&logits[((size_t)b * SS + 1) * NT + lane]) : 0.f;

    for (int t = 1; t < SS; ++t) {
        const float lg = lgnext;
        const int tn = (t + 1 < SS) ? (t + 1) : (SS - 1);
        lgnext = (lane < 9) ? __ldg(&logits[((size_t)b * SS + tn) * NT + lane]) : 0.f;

        float v[9];
        #pragma unroll
        for (int i = 0; i < 9; ++i)
            v[i] = __shfl_sync(FULL, alpha, i) + tr[i];
        // max tree (depth 4)
        float m01 = fmaxf(v[0], v[1]), m23 = fmaxf(v[2], v[3]);
        float m45 = fmaxf(v[4], v[5]), m67 = fmaxf(v[6], v[7]);
        float m = fmaxf(fmaxf(fmaxf(m01, m23), fmaxf(m45, m67)), v[8]);
        float e[9];
        #pragma unroll
        for (int i = 0; i < 9; ++i) e[i] = __expf(v[i] - m);
        // sum tree
        float s01 = e[0] + e[1], s23 = e[2] + e[3], s45 = e[4] + e[5], s67 = e[6] + e[7];
        float ssum = ((s01 + s23) + (s45 + s67)) + e[8];
        const float nv = m + __logf(ssum) + lg;
        if (t < len && lane < 9) alpha = nv;
    }

    float av = (lane < 9) ? alpha : -1e30f;
    float m = av;
    #pragma unroll
    for (int o = 16; o; o >>= 1) m = fmaxf(m, __shfl_xor_sync(FULL, m, o));
    float e = (lane < 9) ? __expf(av - m) : 0.f;
    #pragma unroll
    for (int o = 16; o; o >>= 1) e += __shfl_xor_sync(FULL, e, o);
    const float lognorm = m + __logf(e);

    float sc = 0.f;
    for (int t = lane; t < SS; t += 32) {
        const int lt = labels[b * SS + t];
        if (t < len) sc += logits[((size_t)b * SS + t) * NT + lt];
        if (t < len - 1) sc += trans[lt * 9 + labels[b * SS + t + 1]];
    }
    #pragma unroll
    for (int o = 16; o; o >>= 1) sc += __shfl_xor_sync(FULL, sc, o);

    if (lane == 0) {
        out[(size_t)BB * SS * NT + b]      = (float)len;
        out[(size_t)BB * SS * NT + BB + b] = sc - lognorm;
    }
}

// ---------------------------------------------------------------------------
extern "C" void kernel_launch(void* const* d_in, const int* in_sizes, int n_in,
                              void* d_out, int out_size)
{
    const int*   text   = (const int*)  d_in[0];
    const int*   labels = (const int*)  d_in[1];
    const float* emb    = (const float*)d_in[2];
    const float* W_f    = (const float*)d_in[3];
    const float* U_f    = (const float*)d_in[4];
    const float* b_f    = (const float*)d_in[5];
    const float* W_b    = (const float*)d_in[6];
    const float* U_b    = (const float*)d_in[7];
    const float* b_b    = (const float*)d_in[8];
    const float* W_d    = (const float*)d_in[9];
    const float* b_d    = (const float*)d_in[10];
    const float* trans  = (const float*)d_in[11];
    float* out = (float*)d_out;

    cudaFuncSetAttribute(gemm_xz_kernel, cudaFuncAttributeMaxDynamicSharedMemorySize, 102400);
    cudaFuncSetAttribute(lstm_kernel,    cudaFuncAttributeMaxDynamicSharedMemorySize, 102400);

    gemm_xz_kernel<<<dim3(512, 16), 256, 102400>>>(text, emb, W_f, b_f, W_b, b_b);
    lstm_kernel<<<128, 256, 102400>>>(U_f, U_b);
    logits_kernel<<<512, 256>>>(W_d, b_d, out);
    crf_kernel<<<64, 32>>>(text, labels, trans, out);
}